// round 11
// baseline (speedup 1.0000x reference)
#include <cuda_runtime.h>
#include <cstdint>
#include <mma.h>
#include <math.h>

using namespace nvcuda;

#define B_   4
#define T_   4096
#define D_   1024
#define H_   8
#define BS_  128
#define TB_  2048            /* timesteps per block (half of T) */
#define SC_  64              /* timesteps per GEMM sub-chunk */
#define NSC_ (TB_/SC_)       /* 32 */
#define NCB_ 32              /* channel-blocks: H * 4 quarters */
#define WP_  36              /* weight tile row stride */
#define ZPT_ 68              /* z tile (channel-major) row stride: 64 + 4 pad */
#define XP_  132             /* x tile row stride */

// Scratch (device globals; no allocation allowed). No flags, no spins.
__device__ __align__(16) float g_ylocal[B_*T_*D_];   /* second half only */
__device__ __align__(16) float g_prefix[B_*T_*D_];
__device__ __align__(16) float g_S0[B_*D_];          /* state after first half */
__device__ __align__(16) float g_hP[B_*D_];          /* A-product of second half */
__device__ __align__(16) float g_hY[B_*D_];          /* local Y of second half */

// smem layout (floats)
#define OFF_W1   0
#define OFF_W2   (OFF_W1 + 128*WP_)     /* 4608  */
#define OFF_XS   (OFF_W2 + 128*WP_)     /* 9216  */
#define OFF_Z1   (OFF_XS + SC_*XP_)     /* 17664 */
#define OFF_Z2   (OFF_Z1 + 32*ZPT_)     /* 19840 */
#define OFF_SPS  (OFF_Z2 + 32*ZPT_)     /* 22016 */
#define SMEM_FLOATS (OFF_SPS + 32)      /* 22048 -> 86.1 KB -> 2 CTAs/SM */
#define SMEM_BYTES  (SMEM_FLOATS*4)

__device__ __forceinline__ void cp16(unsigned dst, const float* src) {
    asm volatile("cp.async.cg.shared.global [%0], [%1], 16;" :: "r"(dst), "l"(src));
}

// ---------------------------------------------------------------------------
// K1: block = (gb time-half, channel-block, batch). 32 channels, 2048 steps.
// M=64 GEMM sub-chunks; each warp computes BOTH gates from one A fragment.
// Zero inter-block communication.
// ---------------------------------------------------------------------------
__global__ void __launch_bounds__(256, 2) k1_gemm_scan(
    const float* __restrict__ x, const float* __restrict__ a_param,
    const float* __restrict__ w_in, const float* __restrict__ w_a,
    float* __restrict__ out)
{
    extern __shared__ float sm[];
    float* w1s = sm + OFF_W1;
    float* w2s = sm + OFF_W2;
    float* xs  = sm + OFF_XS;
    float* z1  = sm + OFF_Z1;    // [32 ch][ZPT_] gate_x z (channel-major)
    float* z2  = sm + OFF_Z2;    // [32 ch][ZPT_] gate_a z
    float* sps = sm + OFF_SPS;

    const int b    = blockIdx.z;
    const int cb   = blockIdx.y;
    const int h    = cb >> 2;
    const int q    = cb & 3;
    const int gb   = blockIdx.x;          // 0 or 1
    const int tid  = threadIdx.x;
    const int col0 = h*BS_ + q*32;
    const int t0   = gb*TB_;

    // Stage weights (32 output cols of both gates), tf32 pre-rounded
    {
        const float* w1g = w_in + (size_t)h*BS_*BS_ + q*32;
        const float* w2g = w_a  + (size_t)h*BS_*BS_ + q*32;
        for (int i = tid; i < 128*32; i += 256) {
            int d = i >> 5, e = i & 31;
            w1s[d*WP_ + e] = wmma::__float_to_tf32(w1g[d*BS_ + e]);
            w2s[d*WP_ + e] = wmma::__float_to_tf32(w2g[d*BS_ + e]);
        }
        if (tid < 32) {
            float apv = a_param[col0 + tid];
            sps[tid]  = 8.0f * log1pf(__expf(apv));   // C * softplus(a_param)
        }
    }

    const int warp = tid >> 5;
    const int lane = tid & 31;
    // GEMM mapping: 8 warps = 4 row-blocks (time) x 2 col-halves (channels)
    const int rb   = warp >> 1;        // 0..3: 16-row block of M=64
    const int cq   = warp & 1;         // 0..1: 16-col half of N=32
    // scan mapping: lane = el*8 + sg ; channel e = warp*4 + el; seg len 8
    const int el = lane >> 3;
    const int sg = lane & 7;
    const int e  = warp*4 + el;

    const float* xg_base = x + ((size_t)(b*T_ + t0))*D_ + h*BS_;
    const unsigned xsb = (unsigned)__cvta_generic_to_shared(xs);

    __syncthreads();
    const float spe = sps[e];

    float s_sub = 0.0f;   // block-relative state
    float P_sub = 1.0f;   // running prefix product

    for (int cc = 0; cc < NSC_; ++cc) {
        const int ts = cc*SC_;    // block-relative first timestep

        // ---- stage x tile [SC_][128] (single buffer, 8 cp16/thread) ----
        {
            const float* xg = xg_base + (size_t)ts*D_;
            #pragma unroll
            for (int k = 0; k < 8; ++k) {
                int qq = tid + 256*k;           // 0..2047
                int t  = qq >> 5, c4 = (qq & 31) << 2;
                cp16(xsb + (unsigned)(t*XP_ + c4)*4u, xg + (size_t)t*D_ + c4);
            }
            asm volatile("cp.async.commit_group;");
            asm volatile("cp.async.wait_group 0;");
        }
        __syncthreads();   // tile visible

        // ---- GEMM: M=64, N=32, K=128; both gates share each A fragment ----
        {
            wmma::fragment<wmma::accumulator, 16, 16, 8, float> acc1, acc2;
            wmma::fill_fragment(acc1, 0.0f);
            wmma::fill_fragment(acc2, 0.0f);
            const float* xb = xs + rb*16*XP_;
            #pragma unroll 4
            for (int kk = 0; kk < 16; ++kk) {
                wmma::fragment<wmma::matrix_a, 16, 16, 8, wmma::precision::tf32, wmma::row_major> af;
                wmma::load_matrix_sync(af, xb + kk*8, XP_);
                // NOTE: no per-element CVT — tf32 MMA truncates fp32 mantissa (RZ on A)
                wmma::fragment<wmma::matrix_b, 16, 16, 8, wmma::precision::tf32, wmma::row_major> bf;
                wmma::load_matrix_sync(bf, w1s + kk*8*WP_ + cq*16, WP_);
                wmma::mma_sync(acc1, af, bf, acc1);
                wmma::load_matrix_sync(bf, w2s + kk*8*WP_ + cq*16, WP_);
                wmma::mma_sync(acc2, af, bf, acc2);
            }
            // channel-major store: z[channel][time]
            wmma::store_matrix_sync(z1 + (cq*16)*ZPT_ + rb*16, acc1, ZPT_, wmma::mem_col_major);
            wmma::store_matrix_sync(z2 + (cq*16)*ZPT_ + rb*16, acc2, ZPT_, wmma::mem_col_major);
        }
        __syncthreads();

        // ---- scan lane work: 1 channel x 8 timesteps ----
        {
            float zx[8], za[8];
            {
                const float4 a0 = *reinterpret_cast<const float4*>(z1 + e*ZPT_ + sg*8);
                const float4 a1 = *reinterpret_cast<const float4*>(z1 + e*ZPT_ + sg*8 + 4);
                const float4 b0 = *reinterpret_cast<const float4*>(z2 + e*ZPT_ + sg*8);
                const float4 b1 = *reinterpret_cast<const float4*>(z2 + e*ZPT_ + sg*8 + 4);
                zx[0]=a0.x; zx[1]=a0.y; zx[2]=a0.z; zx[3]=a0.w;
                zx[4]=a1.x; zx[5]=a1.y; zx[6]=a1.z; zx[7]=a1.w;
                za[0]=b0.x; za[1]=b0.y; za[2]=b0.z; za[3]=b0.w;
                za[4]=b1.x; za[5]=b1.y; za[6]=b1.z; za[7]=b1.w;
            }
            const float* xvp = xs + (sg*8)*XP_ + q*32 + e;

            float av[8], bv[8];
            float Pseg = 1.0f, Yseg = 0.0f;
            #pragma unroll
            for (int i = 0; i < 8; ++i) {
                float gi = __fdividef(1.0f, 1.0f + __expf(-zx[i]));
                float ga = __fdividef(1.0f, 1.0f + __expf(-za[i]));
                float la = -spe * ga;
                float a  = __expf(la);
                float m2 = -expm1f(2.0f*la);          // 1 - exp(2*la), accurate
                float mult = sqrtf(fmaxf(m2, 0.0f));
                float bb = mult * gi * xvp[i*XP_];
                av[i] = a; bv[i] = bb;
                Yseg = fmaf(a, Yseg, bb);
                Pseg *= a;
            }
            // Kogge-Stone over 8 segments (width-8 shuffles)
            float Ac = Pseg, Yc = Yseg;
            #pragma unroll
            for (int d = 1; d < 8; d <<= 1) {
                float Ap = __shfl_up_sync(0xffffffffu, Ac, d, 8);
                float Yp = __shfl_up_sync(0xffffffffu, Yc, d, 8);
                if (sg >= d) { Yc = fmaf(Ac, Yp, Yc); Ac *= Ap; }
            }
            float Aex = __shfl_up_sync(0xffffffffu, Ac, 1, 8);
            float Yex = __shfl_up_sync(0xffffffffu, Yc, 1, 8);
            if (sg == 0) { Aex = 1.0f; Yex = 0.0f; }
            const float At = __shfl_sync(0xffffffffu, Ac, 7, 8);
            const float Yt = __shfl_sync(0xffffffffu, Yc, 7, 8);

            float s = fmaf(Aex, s_sub, Yex);
            float P = P_sub * Aex;
            const size_t gbase = ((size_t)(b*T_ + t0 + ts + sg*8))*D_ + col0 + e;
            if (gb == 0) {
                #pragma unroll
                for (int i = 0; i < 8; ++i) {
                    s = fmaf(av[i], s, bv[i]);
                    out[gbase + (size_t)i*D_] = s;    // carry-in is 0: y == local
                }
            } else {
                #pragma unroll
                for (int i = 0; i < 8; ++i) {
                    s = fmaf(av[i], s, bv[i]);
                    P *= av[i];
                    g_ylocal[gbase + (size_t)i*D_] = s;
                    g_prefix[gbase + (size_t)i*D_] = P;
                }
            }
            s_sub = fmaf(At, s_sub, Yt);
            P_sub *= At;
        }
        __syncthreads();   // scan done; x/z reusable next iter
    }

    // publish summaries (no waiting, no flags)
    if (sg == 0) {
        const int gi = b*D_ + col0 + e;
        if (gb == 0) {
            g_S0[gi] = s_sub;                 // state entering second half
        } else {
            g_hP[gi] = P_sub;                 // A-product of second half
            g_hY[gi] = s_sub;                 // local Y of second half
        }
    }
}

// ---------------------------------------------------------------------------
// K2: h_last = A1 * S0 + Y1  (4096 channels)
// ---------------------------------------------------------------------------
__global__ void k2_hlast(float* __restrict__ out)
{
    int i = blockIdx.x*blockDim.x + threadIdx.x;   // 0 .. B*D-1
    out[(size_t)B_*T_*D_ + i] = fmaf(g_hP[i], g_S0[i], g_hY[i]);
}

// ---------------------------------------------------------------------------
// K3: second half only: y = y_local + S0 * prefix  (float4 streaming)
// ---------------------------------------------------------------------------
__global__ void __launch_bounds__(256) k3_apply(float* __restrict__ out)
{
    size_t j = (size_t)blockIdx.x*256 + threadIdx.x;   // over B*(T/2)*(D/4)
    int d4   = (int)(j & 255);                          // D/4 = 256
    size_t r = j >> 8;
    int t    = (int)(r & 2047) + TB_;                   // second half
    int b    = (int)(r >> 11);
    size_t i = ((size_t)(b*T_ + t))*D_ + d4*4;
    const float4 S  = *reinterpret_cast<const float4*>(g_S0 + b*D_ + d4*4);
    const float4 yl = *reinterpret_cast<const float4*>(g_ylocal + i);
    const float4 P  = *reinterpret_cast<const float4*>(g_prefix + i);
    float4 rr;
    rr.x = fmaf(S.x, P.x, yl.x);
    rr.y = fmaf(S.y, P.y, yl.y);
    rr.z = fmaf(S.z, P.z, yl.z);
    rr.w = fmaf(S.w, P.w, yl.w);
    *reinterpret_cast<float4*>(out + i) = rr;
}

extern "C" void kernel_launch(void* const* d_in, const int* in_sizes, int n_in,
                              void* d_out, int out_size)
{
    const float* x  = (const float*)d_in[0];
    const float* ap = (const float*)d_in[1];
    const float* wi = (const float*)d_in[2];
    const float* wa = (const float*)d_in[3];
    float* out = (float*)d_out;

    cudaFuncSetAttribute(k1_gemm_scan,
                         cudaFuncAttributeMaxDynamicSharedMemorySize, SMEM_BYTES);

    k1_gemm_scan<<<dim3(2, NCB_, B_), 256, SMEM_BYTES>>>(x, ap, wi, wa, out);
    k2_hlast<<<(B_*D_)/256, 256>>>(out);
    k3_apply<<<(B_*(T_/2)*(D_/4))/256, 256>>>(out);
}

// round 12
// speedup vs baseline: 1.4185x; 1.4185x over previous
#include <cuda_runtime.h>
#include <cstdint>
#include <mma.h>
#include <math.h>

using namespace nvcuda;

#define B_   4
#define T_   4096
#define D_   1024
#define H_   8
#define BS_  128
#define TB_  2048            /* timesteps per block (half of T) */
#define SC_  32              /* timesteps per GEMM sub-chunk */
#define NSC_ (TB_/SC_)       /* 64 */
#define NCB_ 32              /* channel-blocks: H * 4 quarters */
#define WP_  36              /* weight tile row stride */
#define ZPT_ 36              /* z tile (channel-major) row stride */
#define XP_  132             /* x tile row stride */

// Scratch (device globals; no allocation allowed). No flags, no spins.
__device__ __align__(16) float g_ylocal[B_*T_*D_];   /* second half only */
__device__ __align__(16) float g_prefix[B_*T_*D_];
__device__ __align__(16) float g_S0[B_*D_];          /* state after first half */
__device__ __align__(16) float g_hP[B_*D_];          /* A-product of second half */
__device__ __align__(16) float g_hY[B_*D_];          /* local Y of second half */

// smem layout (floats)
#define OFF_W1   0
#define OFF_W2   (OFF_W1 + 128*WP_)     /* 4608  */
#define OFF_XS0  (OFF_W2 + 128*WP_)     /* 9216  */
#define OFF_XS1  (OFF_XS0 + SC_*XP_)    /* 13440 */
#define OFF_Z1   (OFF_XS1 + SC_*XP_)    /* 17664 */
#define OFF_Z2   (OFF_Z1 + 32*ZPT_)     /* 18816 */
#define OFF_SPS  (OFF_Z2 + 32*ZPT_)     /* 19968 */
#define SMEM_FLOATS (OFF_SPS + 32)      /* 20000 -> 78.1 KB -> 2 CTAs/SM */
#define SMEM_BYTES  (SMEM_FLOATS*4)

__device__ __forceinline__ void cp16(unsigned dst, const float* src) {
    asm volatile("cp.async.cg.shared.global [%0], [%1], 16;" :: "r"(dst), "l"(src));
}

// ---------------------------------------------------------------------------
// K1: block = (gb time-half, channel-block, batch). 32 channels, 2048 steps.
// Two barriers per sub-chunk; no per-element A conversion (tf32 RZ truncate).
// Zero inter-block communication.
// ---------------------------------------------------------------------------
__global__ void __launch_bounds__(256, 2) k1_gemm_scan(
    const float* __restrict__ x, const float* __restrict__ a_param,
    const float* __restrict__ w_in, const float* __restrict__ w_a,
    float* __restrict__ out)
{
    extern __shared__ float sm[];
    float* w1s = sm + OFF_W1;
    float* w2s = sm + OFF_W2;
    float* z1  = sm + OFF_Z1;    // [32 ch][ZPT_] gate_x z (channel-major)
    float* z2  = sm + OFF_Z2;    // [32 ch][ZPT_] gate_a z
    float* sps = sm + OFF_SPS;

    const int b    = blockIdx.z;
    const int cb   = blockIdx.y;
    const int h    = cb >> 2;
    const int q    = cb & 3;
    const int gb   = blockIdx.x;          // 0 or 1
    const int tid  = threadIdx.x;
    const int col0 = h*BS_ + q*32;
    const int t0   = gb*TB_;

    // Stage weights (32 output cols of both gates), tf32 pre-rounded
    {
        const float* w1g = w_in + (size_t)h*BS_*BS_ + q*32;
        const float* w2g = w_a  + (size_t)h*BS_*BS_ + q*32;
        for (int i = tid; i < 128*32; i += 256) {
            int d = i >> 5, e = i & 31;
            w1s[d*WP_ + e] = wmma::__float_to_tf32(w1g[d*BS_ + e]);
            w2s[d*WP_ + e] = wmma::__float_to_tf32(w2g[d*BS_ + e]);
        }
        if (tid < 32) {
            float apv = a_param[col0 + tid];
            sps[tid]  = 8.0f * log1pf(__expf(apv));   // C * softplus(a_param)
        }
    }

    const int warp = tid >> 5;
    const int lane = tid & 31;
    // GEMM mapping
    const int g    = warp >> 2;        // gate 0/1
    const int rb   = (warp >> 1) & 1;  // 16-row block of M=32
    const int cq   = warp & 1;         // 16-col half of N=32
    float* wg = g ? w2s : w1s;
    float* zg = g ? z2  : z1;
    // scan mapping: lane = el*8 + sg ; channel e = warp*4 + el
    const int el = lane >> 3;
    const int sg = lane & 7;
    const int e  = warp*4 + el;

    const float* xg_base = x + ((size_t)(b*T_ + t0))*D_ + h*BS_;
    unsigned xsb[2];
    xsb[0] = (unsigned)__cvta_generic_to_shared(sm + OFF_XS0);
    xsb[1] = (unsigned)__cvta_generic_to_shared(sm + OFF_XS1);
    float* xsf[2] = { sm + OFF_XS0, sm + OFF_XS1 };

    __syncthreads();
    const float spe = sps[e];

    // preload tile 0 into buf 0
    {
        #pragma unroll
        for (int k = 0; k < 4; ++k) {
            int qq = tid + 256*k;
            int t  = qq >> 5, c4 = (qq & 31) << 2;
            cp16(xsb[0] + (unsigned)(t*XP_ + c4)*4u, xg_base + (size_t)t*D_ + c4);
        }
        asm volatile("cp.async.commit_group;");
    }

    float s_sub = 0.0f;   // block-relative state
    float P_sub = 1.0f;   // running prefix product

    for (int cc = 0; cc < NSC_; ++cc) {
        const int buf = cc & 1;
        const int ts  = cc*SC_;    // block-relative first timestep

        // wait: x[buf] landed (committed in previous iteration / prolog)
        asm volatile("cp.async.wait_group 0;");
        __syncthreads();   // SA: x[buf] visible; scan(cc-1) retired (z + x[buf^1] free)

        // issue next tile into buf^1 (overlaps GEMM + scan below)
        if (cc + 1 < NSC_) {
            const float* xg = xg_base + (size_t)(ts + SC_)*D_;
            #pragma unroll
            for (int k = 0; k < 4; ++k) {
                int qq = tid + 256*k;
                int t  = qq >> 5, c4 = (qq & 31) << 2;
                cp16(xsb[buf^1] + (unsigned)(t*XP_ + c4)*4u, xg + (size_t)t*D_ + c4);
            }
            asm volatile("cp.async.commit_group;");
        }

        // ---- GEMM: M=32, N=32, K=128; warps split across gates ----
        {
            wmma::fragment<wmma::accumulator, 16, 16, 8, float> acc;
            wmma::fill_fragment(acc, 0.0f);
            const float* xb = xsf[buf] + rb*16*XP_;
            #pragma unroll 4
            for (int kk = 0; kk < 16; ++kk) {
                wmma::fragment<wmma::matrix_a, 16, 16, 8, wmma::precision::tf32, wmma::row_major> af;
                wmma::load_matrix_sync(af, xb + kk*8, XP_);
                // no per-element CVT: tf32 MMA truncates fp32 mantissa (RZ on A)
                wmma::fragment<wmma::matrix_b, 16, 16, 8, wmma::precision::tf32, wmma::row_major> bf;
                wmma::load_matrix_sync(bf, wg + kk*8*WP_ + cq*16, WP_);
                wmma::mma_sync(acc, af, bf, acc);
            }
            // channel-major store: z[e][t]
            wmma::store_matrix_sync(zg + (cq*16)*ZPT_ + rb*16, acc, ZPT_, wmma::mem_col_major);
        }
        __syncthreads();   // SB: z visible

        // ---- scan lane work: 1 channel x 4 timesteps ----
        {
            const float4 zx4 = *reinterpret_cast<const float4*>(z1 + e*ZPT_ + sg*4);
            const float4 za4 = *reinterpret_cast<const float4*>(z2 + e*ZPT_ + sg*4);
            const float* xvp = xsf[buf] + (sg*4)*XP_ + q*32 + e;

            float av[4], bv[4];
            float Pseg = 1.0f, Yseg = 0.0f;
            const float zx[4] = {zx4.x, zx4.y, zx4.z, zx4.w};
            const float za[4] = {za4.x, za4.y, za4.z, za4.w};
            #pragma unroll
            for (int i = 0; i < 4; ++i) {
                float gi = __fdividef(1.0f, 1.0f + __expf(-zx[i]));
                float ga = __fdividef(1.0f, 1.0f + __expf(-za[i]));
                float la = -spe * ga;
                float a  = __expf(la);
                float m2 = -expm1f(2.0f*la);          // 1 - exp(2*la), accurate
                float mult = sqrtf(fmaxf(m2, 0.0f));
                float bb = mult * gi * xvp[i*XP_];
                av[i] = a; bv[i] = bb;
                Yseg = fmaf(a, Yseg, bb);
                Pseg *= a;
            }
            // Kogge-Stone over 8 segments (width-8 shuffles)
            float Ac = Pseg, Yc = Yseg;
            #pragma unroll
            for (int d = 1; d < 8; d <<= 1) {
                float Ap = __shfl_up_sync(0xffffffffu, Ac, d, 8);
                float Yp = __shfl_up_sync(0xffffffffu, Yc, d, 8);
                if (sg >= d) { Yc = fmaf(Ac, Yp, Yc); Ac *= Ap; }
            }
            float Aex = __shfl_up_sync(0xffffffffu, Ac, 1, 8);
            float Yex = __shfl_up_sync(0xffffffffu, Yc, 1, 8);
            if (sg == 0) { Aex = 1.0f; Yex = 0.0f; }
            const float At = __shfl_sync(0xffffffffu, Ac, 7, 8);
            const float Yt = __shfl_sync(0xffffffffu, Yc, 7, 8);

            float s = fmaf(Aex, s_sub, Yex);
            float P = P_sub * Aex;
            const size_t gbase = ((size_t)(b*T_ + t0 + ts + sg*4))*D_ + col0 + e;
            if (gb == 0) {
                #pragma unroll
                for (int i = 0; i < 4; ++i) {
                    s = fmaf(av[i], s, bv[i]);
                    out[gbase + (size_t)i*D_] = s;    // carry-in is 0: y == local
                }
            } else {
                #pragma unroll
                for (int i = 0; i < 4; ++i) {
                    s = fmaf(av[i], s, bv[i]);
                    P *= av[i];
                    g_ylocal[gbase + (size_t)i*D_] = s;
                    g_prefix[gbase + (size_t)i*D_] = P;
                }
            }
            s_sub = fmaf(At, s_sub, Yt);
            P_sub *= At;
        }
        // no trailing sync: next iteration's SA barrier retires this scan
    }

    // publish summaries (no waiting, no flags)
    if (sg == 0) {
        const int gi = b*D_ + col0 + e;
        if (gb == 0) {
            g_S0[gi] = s_sub;                 // state entering second half
        } else {
            g_hP[gi] = P_sub;                 // A-product of second half
            g_hY[gi] = s_sub;                 // local Y of second half
        }
    }
}

// ---------------------------------------------------------------------------
// K2: h_last = A1 * S0 + Y1  (4096 channels)
// ---------------------------------------------------------------------------
__global__ void k2_hlast(float* __restrict__ out)
{
    int i = blockIdx.x*blockDim.x + threadIdx.x;   // 0 .. B*D-1
    out[(size_t)B_*T_*D_ + i] = fmaf(g_hP[i], g_S0[i], g_hY[i]);
}

// ---------------------------------------------------------------------------
// K3: second half only: y = y_local + S0 * prefix  (float4 streaming)
// ---------------------------------------------------------------------------
__global__ void __launch_bounds__(256) k3_apply(float* __restrict__ out)
{
    size_t j = (size_t)blockIdx.x*256 + threadIdx.x;   // over B*(T/2)*(D/4)
    int d4   = (int)(j & 255);                          // D/4 = 256
    size_t r = j >> 8;
    int t    = (int)(r & 2047) + TB_;                   // second half
    int b    = (int)(r >> 11);
    size_t i = ((size_t)(b*T_ + t))*D_ + d4*4;
    const float4 S  = *reinterpret_cast<const float4*>(g_S0 + b*D_ + d4*4);
    const float4 yl = *reinterpret_cast<const float4*>(g_ylocal + i);
    const float4 P  = *reinterpret_cast<const float4*>(g_prefix + i);
    float4 rr;
    rr.x = fmaf(S.x, P.x, yl.x);
    rr.y = fmaf(S.y, P.y, yl.y);
    rr.z = fmaf(S.z, P.z, yl.z);
    rr.w = fmaf(S.w, P.w, yl.w);
    *reinterpret_cast<float4*>(out + i) = rr;
}

extern "C" void kernel_launch(void* const* d_in, const int* in_sizes, int n_in,
                              void* d_out, int out_size)
{
    const float* x  = (const float*)d_in[0];
    const float* ap = (const float*)d_in[1];
    const float* wi = (const float*)d_in[2];
    const float* wa = (const float*)d_in[3];
    float* out = (float*)d_out;

    cudaFuncSetAttribute(k1_gemm_scan,
                         cudaFuncAttributeMaxDynamicSharedMemorySize, SMEM_BYTES);

    k1_gemm_scan<<<dim3(2, NCB_, B_), 256, SMEM_BYTES>>>(x, ap, wi, wa, out);
    k2_hlast<<<(B_*D_)/256, 256>>>(out);
    k3_apply<<<(B_*(T_/2)*(D_/4))/256, 256>>>(out);
}

// round 14
// speedup vs baseline: 1.4939x; 1.0531x over previous
#include <cuda_runtime.h>
#include <cstdint>
#include <mma.h>
#include <math.h>

using namespace nvcuda;

#define B_   4
#define T_   4096
#define D_   1024
#define H_   8
#define BS_  128
#define TB_  2048            /* timesteps per block (half of T) */
#define SC_  32              /* timesteps per GEMM sub-chunk */
#define NSC_ (TB_/SC_)       /* 64 */
#define NCB_ 32              /* channel-blocks: H * 4 quarters */
#define WP_  36              /* weight tile row stride */
#define ZPT_ 36              /* z tile (time-major) row stride */
#define XP_  132             /* x tile row stride */

// Scratch (device globals; no allocation allowed). No flags, no spins.
__device__ __align__(16) float g_ylocal[B_*T_*D_];   /* second half only */
__device__ __align__(16) float g_prefix[B_*T_*D_];
__device__ __align__(16) float g_S0[B_*D_];          /* state after first half */
__device__ __align__(16) float g_hP[B_*D_];          /* A-product of second half */
__device__ __align__(16) float g_hY[B_*D_];          /* local Y of second half */

// smem layout (floats)
#define OFF_W1   0
#define OFF_W2   (OFF_W1 + 128*WP_)     /* 4608  */
#define OFF_XS0  (OFF_W2 + 128*WP_)     /* 9216  */
#define OFF_XS1  (OFF_XS0 + SC_*XP_)    /* 13440 */
#define OFF_Z1   (OFF_XS1 + SC_*XP_)    /* 17664 */
#define OFF_Z2   (OFF_Z1 + SC_*ZPT_)    /* 18816 */
#define OFF_SGA  (OFF_Z2 + SC_*ZPT_)    /* 19968: segA[8][32] */
#define OFF_SGY  (OFF_SGA + 8*32)       /* 20224: segY[8][32] */
#define OFF_RUNA (OFF_SGY + 8*32)       /* 20480: runA[2][32] (parity) */
#define OFF_RUNY (OFF_RUNA + 2*32)      /* 20544: runY[2][32] */
#define OFF_SPS  (OFF_RUNY + 2*32)      /* 20608 */
#define SMEM_FLOATS (OFF_SPS + 32)      /* 20640 -> 80.6 KB -> 2 CTAs/SM */
#define SMEM_BYTES  (SMEM_FLOATS*4)

__device__ __forceinline__ void cp16(unsigned dst, const float* src) {
    asm volatile("cp.async.cg.shared.global [%0], [%1], 16;" :: "r"(dst), "l"(src));
}

// ---------------------------------------------------------------------------
// K1: block = (gb time-half, channel-block, batch). 32 channels, 2048 steps.
// Scan mapping: warp = 4-step time segment, lane = channel (coalesced STG).
// Zero inter-block communication.
// ---------------------------------------------------------------------------
__global__ void __launch_bounds__(256, 2) k1_gemm_scan(
    const float* __restrict__ x, const float* __restrict__ a_param,
    const float* __restrict__ w_in, const float* __restrict__ w_a,
    float* __restrict__ out)
{
    extern __shared__ float sm[];
    float* w1s  = sm + OFF_W1;
    float* w2s  = sm + OFF_W2;
    float* z1   = sm + OFF_Z1;    // [32 t][ZPT_] gate_x z (time-major)
    float* z2   = sm + OFF_Z2;    // [32 t][ZPT_] gate_a z
    float* segA = sm + OFF_SGA;
    float* segY = sm + OFF_SGY;
    float* runA = sm + OFF_RUNA;  // [2][32] parity ping-pong
    float* runY = sm + OFF_RUNY;
    float* sps  = sm + OFF_SPS;

    const int b    = blockIdx.z;
    const int cb   = blockIdx.y;
    const int h    = cb >> 2;
    const int q    = cb & 3;
    const int gb   = blockIdx.x;          // 0 or 1
    const int tid  = threadIdx.x;
    const int col0 = h*BS_ + q*32;
    const int t0   = gb*TB_;

    // Stage weights (32 output cols of both gates), tf32 pre-rounded
    {
        const float* w1g = w_in + (size_t)h*BS_*BS_ + q*32;
        const float* w2g = w_a  + (size_t)h*BS_*BS_ + q*32;
        for (int i = tid; i < 128*32; i += 256) {
            int d = i >> 5, e = i & 31;
            w1s[d*WP_ + e] = wmma::__float_to_tf32(w1g[d*BS_ + e]);
            w2s[d*WP_ + e] = wmma::__float_to_tf32(w2g[d*BS_ + e]);
        }
        if (tid < 32) {
            float apv = a_param[col0 + tid];
            sps[tid]  = 8.0f * log1pf(__expf(apv));   // C * softplus(a_param)
            runA[tid] = 1.0f;  runA[32 + tid] = 1.0f;
            runY[tid] = 0.0f;  runY[32 + tid] = 0.0f;
        }
    }

    const int warp = tid >> 5;
    const int lane = tid & 31;            // lane == channel for scan phase
    // GEMM mapping
    const int g    = warp >> 2;        // gate 0/1
    const int rb   = (warp >> 1) & 1;  // 16-row (time) block of M=32
    const int cq   = warp & 1;         // 16-col half of N=32
    float* wg = g ? w2s : w1s;
    float* zg = g ? z2  : z1;

    const float* xg_base = x + ((size_t)(b*T_ + t0))*D_ + h*BS_;
    unsigned xsb[2];
    xsb[0] = (unsigned)__cvta_generic_to_shared(sm + OFF_XS0);
    xsb[1] = (unsigned)__cvta_generic_to_shared(sm + OFF_XS1);
    float* xsf[2] = { sm + OFF_XS0, sm + OFF_XS1 };

    __syncthreads();
    const float spe = sps[lane];

    // preload tile 0 into buf 0
    {
        #pragma unroll
        for (int k = 0; k < 4; ++k) {
            int qq = tid + 256*k;
            int t  = qq >> 5, c4 = (qq & 31) << 2;
            cp16(xsb[0] + (unsigned)(t*XP_ + c4)*4u, xg_base + (size_t)t*D_ + c4);
        }
        asm volatile("cp.async.commit_group;");
    }

    for (int cc = 0; cc < NSC_; ++cc) {
        const int buf = cc & 1;
        const int par = cc & 1;
        const int ts  = cc*SC_;    // block-relative first timestep

        asm volatile("cp.async.wait_group 0;");
        __syncthreads();   // SA: x[buf] visible; prev scan fully retired

        // issue next tile into buf^1 (overlaps GEMM + scan below)
        if (cc + 1 < NSC_) {
            const float* xg = xg_base + (size_t)(ts + SC_)*D_;
            #pragma unroll
            for (int k = 0; k < 4; ++k) {
                int qq = tid + 256*k;
                int t  = qq >> 5, c4 = (qq & 31) << 2;
                cp16(xsb[buf^1] + (unsigned)(t*XP_ + c4)*4u, xg + (size_t)t*D_ + c4);
            }
            asm volatile("cp.async.commit_group;");
        }

        // ---- GEMM: M=32, N=32, K=128; warps split across gates ----
        {
            wmma::fragment<wmma::accumulator, 16, 16, 8, float> acc;
            wmma::fill_fragment(acc, 0.0f);
            const float* xb = xsf[buf] + rb*16*XP_;
            #pragma unroll 4
            for (int kk = 0; kk < 16; ++kk) {
                wmma::fragment<wmma::matrix_a, 16, 16, 8, wmma::precision::tf32, wmma::row_major> af;
                wmma::load_matrix_sync(af, xb + kk*8, XP_);
                // no per-element CVT: tf32 MMA truncates fp32 mantissa (RZ on A)
                wmma::fragment<wmma::matrix_b, 16, 16, 8, wmma::precision::tf32, wmma::row_major> bf;
                wmma::load_matrix_sync(bf, wg + kk*8*WP_ + cq*16, WP_);
                wmma::mma_sync(acc, af, bf, acc);
            }
            // time-major store: z[t][channel]
            wmma::store_matrix_sync(zg + (rb*16)*ZPT_ + cq*16, acc, ZPT_, wmma::mem_row_major);
        }
        __syncthreads();   // SB: z visible

        // ---- elementwise + segment summary: warp = 4 timesteps, lane = ch ----
        float av[4], bv[4];
        float Aseg = 1.0f, Yseg = 0.0f;
        {
            #pragma unroll
            for (int i = 0; i < 4; ++i) {
                const int t = warp*4 + i;
                float zx = z1[t*ZPT_ + lane];
                float za = z2[t*ZPT_ + lane];
                float gi = __fdividef(1.0f, 1.0f + __expf(-zx));
                float ga = __fdividef(1.0f, 1.0f + __expf(-za));
                float la = -spe * ga;
                float a  = __expf(la);
                float m2 = -expm1f(2.0f*la);          // 1 - exp(2*la), accurate
                float mult = sqrtf(fmaxf(m2, 0.0f));
                float xv = xsf[buf][t*XP_ + q*32 + lane];
                float bb = mult * gi * xv;
                av[i] = a; bv[i] = bb;
                Yseg = fmaf(a, Yseg, bb);
                Aseg *= a;
            }
            segA[warp*32 + lane] = Aseg;
            segY[warp*32 + lane] = Yseg;
        }
        __syncthreads();   // SC: summaries visible

        // ---- per-warp combine of preceding segments (redundant, no shuffle) ----
        {
            float Ar = runA[par*32 + lane];
            float Yr = runY[par*32 + lane];
            for (int s = 0; s < warp; ++s) {
                float As = segA[s*32 + lane];
                float Ys = segY[s*32 + lane];
                Yr = fmaf(As, Yr, Ys);
                Ar *= As;
            }
            if (warp == 7) {   // publish running state into other parity slot
                runY[(par^1)*32 + lane] = fmaf(Aseg, Yr, Yseg);
                runA[(par^1)*32 + lane] = Ar * Aseg;
            }

            // ---- final 4-step scan + coalesced stores ----
            float s = Yr;
            float P = Ar;
            const size_t gbase = ((size_t)(b*T_ + t0 + ts + warp*4))*D_ + col0 + lane;
            if (gb == 0) {
                #pragma unroll
                for (int i = 0; i < 4; ++i) {
                    s = fmaf(av[i], s, bv[i]);
                    out[gbase + (size_t)i*D_] = s;    // carry-in is 0: y == local
                }
            } else {
                #pragma unroll
                for (int i = 0; i < 4; ++i) {
                    s = fmaf(av[i], s, bv[i]);
                    P *= av[i];
                    g_ylocal[gbase + (size_t)i*D_] = s;
                    g_prefix[gbase + (size_t)i*D_] = P;
                }
            }
        }
        // no trailing sync: next iteration's SA barrier retires this scan
    }

    // FIX (R13 bug): fence warp 7's final parity-0 publish before reading it
    __syncthreads();

    // publish summaries (final running state is in parity NSC_&1 = 0)
    if (tid < 32) {
        const int gi  = b*D_ + col0 + tid;
        const int fin = (NSC_ & 1);
        if (gb == 0) {
            g_S0[gi] = runY[fin*32 + tid];
        } else {
            g_hP[gi] = runA[fin*32 + tid];
            g_hY[gi] = runY[fin*32 + tid];
        }
    }
}

// ---------------------------------------------------------------------------
// K2: h_last = A1 * S0 + Y1  (4096 channels)
// ---------------------------------------------------------------------------
__global__ void k2_hlast(float* __restrict__ out)
{
    int i = blockIdx.x*blockDim.x + threadIdx.x;   // 0 .. B*D-1
    out[(size_t)B_*T_*D_ + i] = fmaf(g_hP[i], g_S0[i], g_hY[i]);
}

// ---------------------------------------------------------------------------
// K3: second half only: y = y_local + S0 * prefix  (float4 streaming)
// ---------------------------------------------------------------------------
__global__ void __launch_bounds__(256) k3_apply(float* __restrict__ out)
{
    size_t j = (size_t)blockIdx.x*256 + threadIdx.x;   // over B*(T/2)*(D/4)
    int d4   = (int)(j & 255);                          // D/4 = 256
    size_t r = j >> 8;
    int t    = (int)(r & 2047) + TB_;                   // second half
    int b    = (int)(r >> 11);
    size_t i = ((size_t)(b*T_ + t))*D_ + d4*4;
    const float4 S  = *reinterpret_cast<const float4*>(g_S0 + b*D_ + d4*4);
    const float4 yl = *reinterpret_cast<const float4*>(g_ylocal + i);
    const float4 P  = *reinterpret_cast<const float4*>(g_prefix + i);
    float4 rr;
    rr.x = fmaf(S.x, P.x, yl.x);
    rr.y = fmaf(S.y, P.y, yl.y);
    rr.z = fmaf(S.z, P.z, yl.z);
    rr.w = fmaf(S.w, P.w, yl.w);
    *reinterpret_cast<float4*>(out + i) = rr;
}

extern "C" void kernel_launch(void* const* d_in, const int* in_sizes, int n_in,
                              void* d_out, int out_size)
{
    const float* x  = (const float*)d_in[0];
    const float* ap = (const float*)d_in[1];
    const float* wi = (const float*)d_in[2];
    const float* wa = (const float*)d_in[3];
    float* out = (float*)d_out;

    cudaFuncSetAttribute(k1_gemm_scan,
                         cudaFuncAttributeMaxDynamicSharedMemorySize, SMEM_BYTES);

    k1_gemm_scan<<<dim3(2, NCB_, B_), 256, SMEM_BYTES>>>(x, ap, wi, wa, out);
    k2_hlast<<<(B_*D_)/256, 256>>>(out);
    k3_apply<<<(B_*(T_/2)*(D_/4))/256, 256>>>(out);
}

// round 15
// speedup vs baseline: 1.5905x; 1.0646x over previous
#include <cuda_runtime.h>
#include <cstdint>
#include <mma.h>
#include <math.h>

using namespace nvcuda;

#define B_   4
#define T_   4096
#define D_   1024
#define H_   8
#define BS_  128
#define TB_  2048            /* timesteps per block (half of T) */
#define SC_  32              /* timesteps per GEMM sub-chunk */
#define NSC_ (TB_/SC_)       /* 64 */
#define NCB_ 32              /* channel-blocks: H * 4 quarters */
#define WP_  36              /* weight tile row stride */
#define ZPT_ 36              /* z tile (time-major) row stride */
#define XP_  132             /* x tile row stride */

// Scratch (device globals; no allocation allowed). No flags, no spins.
__device__ __align__(16) float g_ylocal[B_*T_*D_];   /* second half only */
__device__ __align__(16) float g_prefix[B_*T_*D_];
__device__ __align__(16) float g_S0[B_*D_];          /* state after first half */
__device__ __align__(16) float g_hP[B_*D_];          /* A-product of second half */
__device__ __align__(16) float g_hY[B_*D_];          /* local Y of second half */

// smem layout (floats)
#define OFF_W1   0
#define OFF_W2   (OFF_W1 + 128*WP_)     /* 4608  */
#define OFF_XS0  (OFF_W2 + 128*WP_)     /* 9216  */
#define OFF_XS1  (OFF_XS0 + SC_*XP_)    /* 13440 */
#define OFF_Z1   (OFF_XS1 + SC_*XP_)    /* 17664 */
#define OFF_Z2   (OFF_Z1 + SC_*ZPT_)    /* 18816 */
#define OFF_SGA  (OFF_Z2 + SC_*ZPT_)    /* 19968: segA[8][32] */
#define OFF_SGY  (OFF_SGA + 8*32)       /* 20224: segY[8][32] */
#define OFF_RUNA (OFF_SGY + 8*32)       /* 20480: runA[2][32] (parity) */
#define OFF_RUNY (OFF_RUNA + 2*32)      /* 20544: runY[2][32] */
#define OFF_SPS  (OFF_RUNY + 2*32)      /* 20608 */
#define SMEM_FLOATS (OFF_SPS + 32)      /* 20640 -> 80.6 KB -> 2 CTAs/SM */
#define SMEM_BYTES  (SMEM_FLOATS*4)

__device__ __forceinline__ void cp16(unsigned dst, const float* src) {
    asm volatile("cp.async.cg.shared.global [%0], [%1], 16;" :: "r"(dst), "l"(src));
}
__device__ __forceinline__ float rsqrt_fast(float v) {
    float r; asm("rsqrt.approx.f32 %0, %1;" : "=f"(r) : "f"(v)); return r;
}

// ---------------------------------------------------------------------------
// K1: block = (gb time-half, channel-block, batch). 32 channels, 2048 steps.
// Scan mapping: warp = 4-step time segment, lane = channel (coalesced STG).
// Zero inter-block communication.
// ---------------------------------------------------------------------------
__global__ void __launch_bounds__(256, 2) k1_gemm_scan(
    const float* __restrict__ x, const float* __restrict__ a_param,
    const float* __restrict__ w_in, const float* __restrict__ w_a,
    float* __restrict__ out)
{
    extern __shared__ float sm[];
    float* w1s  = sm + OFF_W1;
    float* w2s  = sm + OFF_W2;
    float* z1   = sm + OFF_Z1;    // [32 t][ZPT_] gate_x z (time-major)
    float* z2   = sm + OFF_Z2;    // [32 t][ZPT_] gate_a z
    float* segA = sm + OFF_SGA;
    float* segY = sm + OFF_SGY;
    float* runA = sm + OFF_RUNA;  // [2][32] parity ping-pong
    float* runY = sm + OFF_RUNY;
    float* sps  = sm + OFF_SPS;

    const int b    = blockIdx.z;
    const int cb   = blockIdx.y;
    const int h    = cb >> 2;
    const int q    = cb & 3;
    const int gb   = blockIdx.x;          // 0 or 1
    const int tid  = threadIdx.x;
    const int col0 = h*BS_ + q*32;
    const int t0   = gb*TB_;

    // Stage weights (32 output cols of both gates), tf32 pre-rounded
    {
        const float* w1g = w_in + (size_t)h*BS_*BS_ + q*32;
        const float* w2g = w_a  + (size_t)h*BS_*BS_ + q*32;
        for (int i = tid; i < 128*32; i += 256) {
            int d = i >> 5, e = i & 31;
            w1s[d*WP_ + e] = wmma::__float_to_tf32(w1g[d*BS_ + e]);
            w2s[d*WP_ + e] = wmma::__float_to_tf32(w2g[d*BS_ + e]);
        }
        if (tid < 32) {
            float apv = a_param[col0 + tid];
            sps[tid]  = 8.0f * log1pf(__expf(apv));   // C * softplus(a_param)
            runA[tid] = 1.0f;  runA[32 + tid] = 1.0f;
            runY[tid] = 0.0f;  runY[32 + tid] = 0.0f;
        }
    }

    const int warp = tid >> 5;
    const int lane = tid & 31;            // lane == channel for scan phase
    // GEMM mapping
    const int g    = warp >> 2;        // gate 0/1
    const int rb   = (warp >> 1) & 1;  // 16-row (time) block of M=32
    const int cq   = warp & 1;         // 16-col half of N=32
    float* wg = g ? w2s : w1s;
    float* zg = g ? z2  : z1;

    const float* xg_base = x + ((size_t)(b*T_ + t0))*D_ + h*BS_;
    unsigned xsb[2];
    xsb[0] = (unsigned)__cvta_generic_to_shared(sm + OFF_XS0);
    xsb[1] = (unsigned)__cvta_generic_to_shared(sm + OFF_XS1);
    float* xsf[2] = { sm + OFF_XS0, sm + OFF_XS1 };

    __syncthreads();
    const float spe = sps[lane];

    // preload tile 0 into buf 0
    {
        #pragma unroll
        for (int k = 0; k < 4; ++k) {
            int qq = tid + 256*k;
            int t  = qq >> 5, c4 = (qq & 31) << 2;
            cp16(xsb[0] + (unsigned)(t*XP_ + c4)*4u, xg_base + (size_t)t*D_ + c4);
        }
        asm volatile("cp.async.commit_group;");
    }

    for (int cc = 0; cc < NSC_; ++cc) {
        const int buf = cc & 1;
        const int par = cc & 1;
        const int ts  = cc*SC_;    // block-relative first timestep

        asm volatile("cp.async.wait_group 0;");
        __syncthreads();   // SA: x[buf] visible; prev scan fully retired

        // issue next tile into buf^1 (overlaps GEMM + scan below)
        if (cc + 1 < NSC_) {
            const float* xg = xg_base + (size_t)(ts + SC_)*D_;
            #pragma unroll
            for (int k = 0; k < 4; ++k) {
                int qq = tid + 256*k;
                int t  = qq >> 5, c4 = (qq & 31) << 2;
                cp16(xsb[buf^1] + (unsigned)(t*XP_ + c4)*4u, xg + (size_t)t*D_ + c4);
            }
            asm volatile("cp.async.commit_group;");
        }

        // ---- GEMM: M=32, N=32, K=128; warps split across gates ----
        {
            wmma::fragment<wmma::accumulator, 16, 16, 8, float> acc;
            wmma::fill_fragment(acc, 0.0f);
            const float* xb = xsf[buf] + rb*16*XP_;
            #pragma unroll 4
            for (int kk = 0; kk < 16; ++kk) {
                wmma::fragment<wmma::matrix_a, 16, 16, 8, wmma::precision::tf32, wmma::row_major> af;
                wmma::load_matrix_sync(af, xb + kk*8, XP_);
                // no per-element CVT: tf32 MMA truncates fp32 mantissa (RZ on A)
                wmma::fragment<wmma::matrix_b, 16, 16, 8, wmma::precision::tf32, wmma::row_major> bf;
                wmma::load_matrix_sync(bf, wg + kk*8*WP_ + cq*16, WP_);
                wmma::mma_sync(acc, af, bf, acc);
            }
            // time-major store: z[t][channel]
            wmma::store_matrix_sync(zg + (rb*16)*ZPT_ + cq*16, acc, ZPT_, wmma::mem_row_major);
        }
        __syncthreads();   // SB: z visible

        // ---- elementwise + segment summary: warp = 4 timesteps, lane = ch ----
        float av[4], bv[4];
        float Aseg = 1.0f, Yseg = 0.0f;
        {
            #pragma unroll
            for (int i = 0; i < 4; ++i) {
                const int t = warp*4 + i;
                float zx = z1[t*ZPT_ + lane];
                float za = z2[t*ZPT_ + lane];
                float gi = __fdividef(1.0f, 1.0f + __expf(-zx));
                float ga = __fdividef(1.0f, 1.0f + __expf(-za));
                float a  = __expf(-spe * ga);
                // 1 - a^2 : same fp32 cancellation class as reference's
                // sqrt(1 - exp(2*log_a)); guard against a==1.0 -> 0*inf
                float m2 = fmaxf(fmaf(-a, a, 1.0f), 1e-30f);
                float mult = m2 * rsqrt_fast(m2);     // sqrt(m2), 2 instrs
                float xv = xsf[buf][t*XP_ + q*32 + lane];
                float bb = mult * gi * xv;
                av[i] = a; bv[i] = bb;
                Yseg = fmaf(a, Yseg, bb);
                Aseg *= a;
            }
            segA[warp*32 + lane] = Aseg;
            segY[warp*32 + lane] = Yseg;
        }
        __syncthreads();   // SC: summaries visible

        // ---- per-warp combine of preceding segments (redundant, no shuffle) ----
        {
            float Ar = runA[par*32 + lane];
            float Yr = runY[par*32 + lane];
            for (int s = 0; s < warp; ++s) {
                float As = segA[s*32 + lane];
                float Ys = segY[s*32 + lane];
                Yr = fmaf(As, Yr, Ys);
                Ar *= As;
            }
            if (warp == 7) {   // publish running state into other parity slot
                runY[(par^1)*32 + lane] = fmaf(Aseg, Yr, Yseg);
                runA[(par^1)*32 + lane] = Ar * Aseg;
            }

            // ---- final 4-step scan + coalesced stores ----
            float s = Yr;
            float P = Ar;
            const size_t gbase = ((size_t)(b*T_ + t0 + ts + warp*4))*D_ + col0 + lane;
            if (gb == 0) {
                #pragma unroll
                for (int i = 0; i < 4; ++i) {
                    s = fmaf(av[i], s, bv[i]);
                    out[gbase + (size_t)i*D_] = s;    // carry-in is 0: y == local
                }
            } else {
                #pragma unroll
                for (int i = 0; i < 4; ++i) {
                    s = fmaf(av[i], s, bv[i]);
                    P *= av[i];
                    g_ylocal[gbase + (size_t)i*D_] = s;
                    g_prefix[gbase + (size_t)i*D_] = P;
                }
            }
        }
        // no trailing sync: next iteration's SA barrier retires this scan
    }

    // fence warp 7's final parity-0 publish before reading it
    __syncthreads();

    // publish summaries (final running state is in parity NSC_&1 = 0)
    if (tid < 32) {
        const int gi  = b*D_ + col0 + tid;
        const int fin = (NSC_ & 1);
        if (gb == 0) {
            g_S0[gi] = runY[fin*32 + tid];
        } else {
            g_hP[gi] = runA[fin*32 + tid];
            g_hY[gi] = runY[fin*32 + tid];
        }
    }
}

// ---------------------------------------------------------------------------
// K2: h_last = A1 * S0 + Y1  (4096 channels)
// ---------------------------------------------------------------------------
__global__ void k2_hlast(float* __restrict__ out)
{
    int i = blockIdx.x*blockDim.x + threadIdx.x;   // 0 .. B*D-1
    out[(size_t)B_*T_*D_ + i] = fmaf(g_hP[i], g_S0[i], g_hY[i]);
}

// ---------------------------------------------------------------------------
// K3: second half only: y = y_local + S0 * prefix  (float4 streaming)
// ---------------------------------------------------------------------------
__global__ void __launch_bounds__(256) k3_apply(float* __restrict__ out)
{
    size_t j = (size_t)blockIdx.x*256 + threadIdx.x;   // over B*(T/2)*(D/4)
    int d4   = (int)(j & 255);                          // D/4 = 256
    size_t r = j >> 8;
    int t    = (int)(r & 2047) + TB_;                   // second half
    int b    = (int)(r >> 11);
    size_t i = ((size_t)(b*T_ + t))*D_ + d4*4;
    const float4 S  = *reinterpret_cast<const float4*>(g_S0 + b*D_ + d4*4);
    const float4 yl = *reinterpret_cast<const float4*>(g_ylocal + i);
    const float4 P  = *reinterpret_cast<const float4*>(g_prefix + i);
    float4 rr;
    rr.x = fmaf(S.x, P.x, yl.x);
    rr.y = fmaf(S.y, P.y, yl.y);
    rr.z = fmaf(S.z, P.z, yl.z);
    rr.w = fmaf(S.w, P.w, yl.w);
    *reinterpret_cast<float4*>(out + i) = rr;
}

extern "C" void kernel_launch(void* const* d_in, const int* in_sizes, int n_in,
                              void* d_out, int out_size)
{
    const float* x  = (const float*)d_in[0];
    const float* ap = (const float*)d_in[1];
    const float* wi = (const float*)d_in[2];
    const float* wa = (const float*)d_in[3];
    float* out = (float*)d_out;

    cudaFuncSetAttribute(k1_gemm_scan,
                         cudaFuncAttributeMaxDynamicSharedMemorySize, SMEM_BYTES);

    k1_gemm_scan<<<dim3(2, NCB_, B_), 256, SMEM_BYTES>>>(x, ap, wi, wa, out);
    k2_hlast<<<(B_*D_)/256, 256>>>(out);
    k3_apply<<<(B_*(T_/2)*(D_/4))/256, 256>>>(out);
}